// round 4
// baseline (speedup 1.0000x reference)
#include <cuda_runtime.h>

// cumprod along dim 1 of a (4096, 8192) fp32 matrix.
// One CTA (256 threads) per row, 32 elements/thread, staged through
// XOR-swizzled shared memory. Local prefixes are written back to the smem
// buffer IN PLACE (chunk slots are thread-private), so no vals[32] register
// array is needed -> ~28 regs -> 6 CTAs/SM for latency hiding.

#define ROW_LEN      8192
#define THREADS      256
#define VECS_PT      8                   // float4 per thread
#define NVEC         (ROW_LEN / 4)       // 2048 float4 per row
#define NWARPS       (THREADS / 32)      // 8

// XOR swizzle on float4 index: low 3 bits permuted by bits [5:3].
// Conflict-free for both the linear phase (j = i*256 + t) and the
// chunk-strided phase (j = 8*t + i).
__device__ __forceinline__ int swz(int j) { return j ^ ((j >> 3) & 7); }

__global__ void __launch_bounds__(THREADS, 6)
cumprod_dim1_kernel(const float* __restrict__ x, float* __restrict__ y) {
    __shared__ float4 buf[NVEC];          // 32 KB row buffer
    __shared__ float  wtot[NWARPS];       // per-warp totals
    __shared__ float  pref[THREADS];      // per-thread exclusive chunk prefixes

    const int t    = threadIdx.x;
    const int lane = t & 31;
    const int wid  = t >> 5;

    const size_t row_off = (size_t)blockIdx.x * ROW_LEN;
    const float4* __restrict__ xin  = reinterpret_cast<const float4*>(x + row_off);
    float4* __restrict__       yout = reinterpret_cast<float4*>(y + row_off);

    // ---- phase 1: coalesced gmem -> swizzled smem ----
    #pragma unroll
    for (int i = 0; i < VECS_PT; i++) {
        int j = i * THREADS + t;
        buf[swz(j)] = __ldcs(&xin[j]);
    }
    __syncthreads();

    // ---- phase 2: in-place local inclusive prefix over own 32-elem chunk ----
    float p = 1.0f;
    #pragma unroll
    for (int i = 0; i < VECS_PT; i++) {
        int s = swz(t * VECS_PT + i);
        float4 v = buf[s];
        v.x *= p;
        v.y *= v.x;
        v.z *= v.y;
        v.w *= v.z;
        p = v.w;
        buf[s] = v;                        // own slots: no race
    }

    // ---- warp-level inclusive scan (product) of per-thread totals ----
    float incl = p;
    #pragma unroll
    for (int o = 1; o < 32; o <<= 1) {
        float v = __shfl_up_sync(0xffffffffu, incl, o);
        if (lane >= o) incl *= v;
    }
    if (lane == 31) wtot[wid] = incl;
    __syncthreads();                       // buf prefixes + wtot visible

    // ---- per-thread exclusive prefix: cross-warp (direct product) * in-warp ----
    float wexcl = 1.0f;
    #pragma unroll
    for (int w = 0; w < NWARPS - 1; w++) {
        float wt = wtot[w];
        if (w < wid) wexcl *= wt;
    }
    float lexcl = __shfl_up_sync(0xffffffffu, incl, 1);
    if (lane == 0) lexcl = 1.0f;
    pref[t] = wexcl * lexcl;
    __syncthreads();                       // pref visible to all

    // ---- phase 3: linear smem read, scale by chunk-owner prefix, coalesced STG ----
    #pragma unroll
    for (int i = 0; i < VECS_PT; i++) {
        int j = i * THREADS + t;
        float4 v = buf[swz(j)];
        float sc = pref[j >> 3];           // owner of float4 j (broadcast-friendly)
        v.x *= sc; v.y *= sc; v.z *= sc; v.w *= sc;
        __stcs(&yout[j], v);
    }
}

extern "C" void kernel_launch(void* const* d_in, const int* in_sizes, int n_in,
                              void* d_out, int out_size) {
    const float* x = (const float*)d_in[0];
    float* y = (float*)d_out;
    const int rows = in_sizes[0] / ROW_LEN;   // 4096
    cumprod_dim1_kernel<<<rows, THREADS>>>(x, y);
}

// round 5
// speedup vs baseline: 1.0475x; 1.0475x over previous
#include <cuda_runtime.h>

// cumprod along dim 1 of a (4096, 8192) fp32 matrix.
// WARP-PER-ROW, no shared memory, no barriers. Each warp walks its row in
// 64 chunks of 128 floats (lane-coalesced float4). Per chunk: per-thread
// 3-FMUL local prefix, 5-step shfl scan of thread totals, scale by running
// carry, coalesced STG.128. The only serial cross-chunk dependence is one
// FMUL (carry *= chunk_total); loads are software-pipelined 4 chunks ahead.

#define ROW_LEN   8192
#define THREADS   128                 // 4 warps/CTA, one row per warp
#define WARPS_CTA (THREADS / 32)
#define CHUNKS    (ROW_LEN / 128)     // 64 chunks of 32 float4
#define GROUP     4                   // pipeline group (chunks)
#define NGROUP    (CHUNKS / GROUP)    // 16

__global__ void __launch_bounds__(THREADS, 8)
cumprod_dim1_kernel(const float* __restrict__ x, float* __restrict__ y) {
    const int lane = threadIdx.x & 31;
    const int row  = blockIdx.x * WARPS_CTA + (threadIdx.x >> 5);

    const size_t row_off = (size_t)row * ROW_LEN;
    const float4* __restrict__ xin  = reinterpret_cast<const float4*>(x + row_off);
    float4* __restrict__       yout = reinterpret_cast<float4*>(y + row_off);

    float carry = 1.0f;
    float4 cur[GROUP], nxt[GROUP];

    // prologue: load group 0 (front-batched, MLP=4)
    #pragma unroll
    for (int i = 0; i < GROUP; i++)
        cur[i] = __ldcs(&xin[i * 32 + lane]);

    #pragma unroll 1
    for (int g = 0; g < NGROUP; g++) {
        // prefetch next group while processing current
        if (g + 1 < NGROUP) {
            const float4* p = &xin[(g + 1) * GROUP * 32 + lane];
            #pragma unroll
            for (int i = 0; i < GROUP; i++)
                nxt[i] = __ldcs(&p[i * 32]);
        }

        #pragma unroll
        for (int i = 0; i < GROUP; i++) {
            float4 v = cur[i];
            // local inclusive prefix within the thread's 4 elements
            v.y *= v.x;
            v.z *= v.y;
            v.w *= v.z;

            // warp inclusive scan (product) of per-thread totals
            float s = v.w;
            #pragma unroll
            for (int o = 1; o < 32; o <<= 1) {
                float t2 = __shfl_up_sync(0xffffffffu, s, o);
                if (lane >= o) s *= t2;
            }
            // exclusive prefix for this thread; chunk total from lane 31
            float e = __shfl_up_sync(0xffffffffu, s, 1);
            if (lane == 0) e = 1.0f;
            float tot = __shfl_sync(0xffffffffu, s, 31);

            const float ce = carry * e;
            float4 o4;
            o4.x = v.x * ce;
            o4.y = v.y * ce;
            o4.z = v.z * ce;
            o4.w = v.w * ce;
            __stcs(&yout[(g * GROUP + i) * 32 + lane], o4);

            carry *= tot;                 // only serial cross-chunk dep (1 FMUL)
        }

        #pragma unroll
        for (int i = 0; i < GROUP; i++)
            cur[i] = nxt[i];
    }
}

extern "C" void kernel_launch(void* const* d_in, const int* in_sizes, int n_in,
                              void* d_out, int out_size) {
    const float* x = (const float*)d_in[0];
    float* y = (float*)d_out;
    const int rows = in_sizes[0] / ROW_LEN;          // 4096
    cumprod_dim1_kernel<<<rows / WARPS_CTA, THREADS>>>(x, y);
}

// round 6
// speedup vs baseline: 1.0604x; 1.0123x over previous
#include <cuda_runtime.h>

// cumprod along dim 1 of a (4096, 8192) fp32 matrix.
// Warp-per-row, no smem, no barriers. Row walked in 64 chunks of 128 floats
// (one float4 per lane). Ring-buffer software pipeline of depth 8 keeps
// 7-8 LDG.128 outstanding per warp at ALL times (no group-drain sawtooth).
// 64-thread CTAs (2 warps) for fine-grained wave balance (2048 CTAs).

#define ROW_LEN   8192
#define THREADS   64                  // 2 warps/CTA, one row per warp
#define WARPS_CTA (THREADS / 32)
#define CHUNKS    (ROW_LEN / 128)     // 64 chunks of 32 float4
#define DEPTH     8                   // pipeline depth (chunks in flight)
#define NOUTER    (CHUNKS / DEPTH)    // 8

__global__ void __launch_bounds__(THREADS)
cumprod_dim1_kernel(const float* __restrict__ x, float* __restrict__ y) {
    const int lane = threadIdx.x & 31;
    const int row  = blockIdx.x * WARPS_CTA + (threadIdx.x >> 5);

    const size_t row_off = (size_t)row * ROW_LEN;
    const float4* __restrict__ xin  = reinterpret_cast<const float4*>(x + row_off);
    float4* __restrict__       yout = reinterpret_cast<float4*>(y + row_off);

    float carry = 1.0f;
    float4 buf[DEPTH];

    // prologue: front-batched loads for chunks 0..7 (MLP=8)
    #pragma unroll
    for (int k = 0; k < DEPTH; k++)
        buf[k] = __ldcs(&xin[k * 32 + lane]);

    #pragma unroll 1
    for (int gg = 0; gg < NOUTER; gg++) {
        const bool more = (gg + 1 < NOUTER);
        #pragma unroll
        for (int k = 0; k < DEPTH; k++) {
            const int g = gg * DEPTH + k;
            float4 v = buf[k];

            // refill this slot immediately: keep 8 loads in flight
            if (more)
                buf[k] = __ldcs(&xin[(g + DEPTH) * 32 + lane]);

            // local inclusive prefix within the thread's 4 elements
            v.y *= v.x;
            v.z *= v.y;
            v.w *= v.z;

            // warp inclusive scan (product) of per-thread totals
            float s = v.w;
            #pragma unroll
            for (int o = 1; o < 32; o <<= 1) {
                float t2 = __shfl_up_sync(0xffffffffu, s, o);
                if (lane >= o) s *= t2;
            }
            float e   = __shfl_up_sync(0xffffffffu, s, 1);
            if (lane == 0) e = 1.0f;
            float tot = __shfl_sync(0xffffffffu, s, 31);

            const float ce = carry * e;
            float4 o4;
            o4.x = v.x * ce;
            o4.y = v.y * ce;
            o4.z = v.z * ce;
            o4.w = v.w * ce;
            __stcs(&yout[g * 32 + lane], o4);

            carry *= tot;              // only serial cross-chunk dep (1 FMUL)
        }
    }
}

extern "C" void kernel_launch(void* const* d_in, const int* in_sizes, int n_in,
                              void* d_out, int out_size) {
    const float* x = (const float*)d_in[0];
    float* y = (float*)d_out;
    const int rows = in_sizes[0] / ROW_LEN;            // 4096
    cumprod_dim1_kernel<<<rows / WARPS_CTA, THREADS>>>(x, y);
}

// round 7
// speedup vs baseline: 1.1623x; 1.0961x over previous
#include <cuda_runtime.h>

// cumprod along dim 1 of a (4096, 8192) fp32 matrix.
// CTA-per-row, 256 threads = 8 warps. Warp w owns the contiguous segment
// [1024w, 1024w+1024). Loads stream gmem->regs (ring pipeline, depth 4,
// coalesced); each 128-float chunk is scanned in flight (local prefix +
// 5-step shfl scan + running carry) and the warp-local result written ONCE
// to linear smem (conflict-free). One barrier, 8-wide segment prefix, then
// a linear smem->gmem output pass with a per-iteration broadcast scale.

#define ROW_LEN  8192
#define THREADS  256
#define NWARPS   8
#define SEG_VEC  256                  // float4 per warp segment
#define CHUNKS   8                    // chunks of 32 float4 per segment
#define DEPTH    4                    // load ring depth
#define NVEC     (ROW_LEN / 4)        // 2048 float4 per row

__global__ void __launch_bounds__(THREADS, 5)
cumprod_dim1_kernel(const float* __restrict__ x, float* __restrict__ y) {
    __shared__ float4 buf[NVEC];      // 32 KB: scanned (warp-local) results
    __shared__ float  wtot[NWARPS];   // per-segment totals

    const int t    = threadIdx.x;
    const int lane = t & 31;
    const int w    = t >> 5;

    const size_t row_off = (size_t)blockIdx.x * ROW_LEN;
    const float4* __restrict__ xin  = reinterpret_cast<const float4*>(x + row_off);
    float4* __restrict__       yout = reinterpret_cast<float4*>(y + row_off);

    const int seg = w * SEG_VEC;      // float4 base of this warp's segment

    // ---- ring prologue: 4 chunk-loads in flight ----
    float4 ring[DEPTH];
    #pragma unroll
    for (int k = 0; k < DEPTH; k++)
        ring[k] = __ldcs(&xin[seg + k * 32 + lane]);

    // ---- scan the 8 chunks while streaming loads ----
    float carry = 1.0f;
    #pragma unroll
    for (int c = 0; c < CHUNKS; c++) {
        float4 v = ring[c & (DEPTH - 1)];
        if (c + DEPTH < CHUNKS)
            ring[c & (DEPTH - 1)] = __ldcs(&xin[seg + (c + DEPTH) * 32 + lane]);

        // local inclusive prefix within the thread's 4 elements
        v.y *= v.x;
        v.z *= v.y;
        v.w *= v.z;

        // warp inclusive scan (product) of per-thread totals
        float s = v.w;
        #pragma unroll
        for (int o = 1; o < 32; o <<= 1) {
            float tv = __shfl_up_sync(0xffffffffu, s, o);
            if (lane >= o) s *= tv;
        }
        float e   = __shfl_up_sync(0xffffffffu, s, 1);
        if (lane == 0) e = 1.0f;
        float tot = __shfl_sync(0xffffffffu, s, 31);

        const float ce = carry * e;
        float4 o4;
        o4.x = v.x * ce;
        o4.y = v.y * ce;
        o4.z = v.z * ce;
        o4.w = v.w * ce;
        buf[seg + c * 32 + lane] = o4;   // linear, conflict-free STS.128

        carry *= tot;                    // segment-local running product
    }
    if (lane == 0) wtot[w] = carry;      // segment total
    __syncthreads();

    // ---- 8-wide exclusive segment prefixes (every thread, broadcast LDS) ----
    float w0 = wtot[0], w1 = wtot[1], w2 = wtot[2], w3 = wtot[3];
    float w4 = wtot[4], w5 = wtot[5], w6 = wtot[6];
    float sp[NWARPS];
    sp[0] = 1.0f;
    sp[1] = w0;
    sp[2] = sp[1] * w1;
    sp[3] = sp[2] * w2;
    sp[4] = sp[3] * w3;
    sp[5] = sp[4] * w4;
    sp[6] = sp[5] * w5;
    sp[7] = sp[6] * w6;

    // ---- linear output: iteration i covers segment i (uniform scale) ----
    #pragma unroll
    for (int i = 0; i < NWARPS; i++) {
        int j = i * THREADS + t;         // == i*256 + t, segment i
        float4 v = buf[j];
        const float sc = sp[i];
        v.x *= sc; v.y *= sc; v.z *= sc; v.w *= sc;
        __stcs(&yout[j], v);
    }
}

extern "C" void kernel_launch(void* const* d_in, const int* in_sizes, int n_in,
                              void* d_out, int out_size) {
    const float* x = (const float*)d_in[0];
    float* y = (float*)d_out;
    const int rows = in_sizes[0] / ROW_LEN;   // 4096
    cumprod_dim1_kernel<<<rows, THREADS>>>(x, y);
}

// round 8
// speedup vs baseline: 1.1774x; 1.0130x over previous
#include <cuda_runtime.h>

// cumprod along dim 1 of a (4096, 8192) fp32 matrix.
// CTA-per-row, 256 threads = 8 warps. Warp w owns floats [1024w, 1024w+1024),
// split into 8 chunks of 128; lane L owns float4 L of each chunk, so gmem
// loads AND stores are natively coalesced and the scanned values stay in
// registers end-to-end. NO smem data staging (only 8 segment totals), ONE
// barrier. Loads are front-batched (8 LDG.128 in flight per warp).

#define ROW_LEN  8192
#define THREADS  256
#define NWARPS   8
#define CHUNKS   8                    // 128-float chunks per warp segment
#define SEG_VEC  256                  // float4 per warp segment

__global__ void __launch_bounds__(THREADS)
cumprod_dim1_kernel(const float* __restrict__ x, float* __restrict__ y) {
    __shared__ float wtot[NWARPS];

    const int t    = threadIdx.x;
    const int lane = t & 31;
    const int w    = t >> 5;

    const size_t row_off = (size_t)blockIdx.x * ROW_LEN;
    const float4* __restrict__ xin  = reinterpret_cast<const float4*>(x + row_off);
    float4* __restrict__       yout = reinterpret_cast<float4*>(y + row_off);

    const int seg = w * SEG_VEC;      // float4 base of this warp's segment

    // ---- front-batched loads: 8 LDG.128 in flight ----
    float4 vals[CHUNKS];
    #pragma unroll
    for (int c = 0; c < CHUNKS; c++)
        vals[c] = __ldcs(&xin[seg + c * 32 + lane]);

    // ---- scan chunks in registers (segment-local running carry) ----
    float carry = 1.0f;
    #pragma unroll
    for (int c = 0; c < CHUNKS; c++) {
        float4 v = vals[c];
        // local inclusive prefix within the thread's 4 elements
        v.y *= v.x;
        v.z *= v.y;
        v.w *= v.z;

        // warp inclusive scan (product) of per-thread totals
        float s = v.w;
        #pragma unroll
        for (int o = 1; o < 32; o <<= 1) {
            float tv = __shfl_up_sync(0xffffffffu, s, o);
            if (lane >= o) s *= tv;
        }
        float e   = __shfl_up_sync(0xffffffffu, s, 1);
        if (lane == 0) e = 1.0f;
        float tot = __shfl_sync(0xffffffffu, s, 31);

        const float ce = carry * e;   // segment-local exclusive prefix
        v.x *= ce; v.y *= ce; v.z *= ce; v.w *= ce;
        vals[c] = v;

        carry *= tot;
    }
    if (lane == 0) wtot[w] = carry;   // segment total
    __syncthreads();

    // ---- cross-warp exclusive prefix (uniform per warp, broadcast LDS) ----
    float pre = 1.0f;
    #pragma unroll
    for (int ww = 0; ww < NWARPS - 1; ww++) {
        float wt = wtot[ww];
        if (ww < w) pre *= wt;
    }

    // ---- scale and store straight from registers (coalesced STG.128) ----
    #pragma unroll
    for (int c = 0; c < CHUNKS; c++) {
        float4 v = vals[c];
        v.x *= pre; v.y *= pre; v.z *= pre; v.w *= pre;
        __stcs(&yout[seg + c * 32 + lane], v);
    }
}

extern "C" void kernel_launch(void* const* d_in, const int* in_sizes, int n_in,
                              void* d_out, int out_size) {
    const float* x = (const float*)d_in[0];
    float* y = (float*)d_out;
    const int rows = in_sizes[0] / ROW_LEN;   // 4096
    cumprod_dim1_kernel<<<rows, THREADS>>>(x, y);
}

// round 9
// speedup vs baseline: 1.1928x; 1.0131x over previous
#include <cuda_runtime.h>

// cumprod along dim 1 of a (4096, 8192) fp32 matrix.
// CTA-per-row, 256 threads = 8 warps. Warp w owns floats [1024w, 1024w+1024);
// lane L owns float4 L of each 128-float chunk -> loads AND stores natively
// coalesced, values register-resident end-to-end. Segment totals are computed
// EARLY (order-independent tree product + butterfly reduce), so the barrier
// fires right after the loads; the scan+scale+store pass runs after it with
// the cross-warp prefix already folded into the carry.

#define ROW_LEN  8192
#define THREADS  256
#define NWARPS   8
#define CHUNKS   8                    // 128-float chunks per warp segment
#define SEG_VEC  256                  // float4 per warp segment

__global__ void __launch_bounds__(THREADS, 5)
cumprod_dim1_kernel(const float* __restrict__ x, float* __restrict__ y) {
    __shared__ float wtot[NWARPS];

    const int t    = threadIdx.x;
    const int lane = t & 31;
    const int w    = t >> 5;

    const size_t row_off = (size_t)blockIdx.x * ROW_LEN;
    const float4* __restrict__ xin  = reinterpret_cast<const float4*>(x + row_off);
    float4* __restrict__       yout = reinterpret_cast<float4*>(y + row_off);

    const int seg = w * SEG_VEC;      // float4 base of this warp's segment

    // ---- front-batched loads: 8 LDG.128 in flight ----
    float4 vals[CHUNKS];
    #pragma unroll
    for (int c = 0; c < CHUNKS; c++)
        vals[c] = __ldcs(&xin[seg + c * 32 + lane]);

    // ---- EARLY segment total: order-independent tree product ----
    float tp = 1.0f;
    #pragma unroll
    for (int c = 0; c < CHUNKS; c++) {
        float4 v = vals[c];
        tp *= (v.x * v.y) * (v.z * v.w);
    }
    #pragma unroll
    for (int o = 1; o < 32; o <<= 1)
        tp *= __shfl_xor_sync(0xffffffffu, tp, o);
    if (lane == 0) wtot[w] = tp;
    __syncthreads();

    // ---- cross-warp exclusive prefix, folded into the running carry ----
    float carry = 1.0f;
    #pragma unroll
    for (int ww = 0; ww < NWARPS - 1; ww++) {
        float wt = wtot[ww];
        if (ww < w) carry *= wt;
    }

    // ---- scan + scale + store, single pass ----
    #pragma unroll
    for (int c = 0; c < CHUNKS; c++) {
        float4 v = vals[c];
        // local inclusive prefix within the thread's 4 elements
        v.y *= v.x;
        v.z *= v.y;
        v.w *= v.z;

        // warp inclusive scan (product) of per-thread totals
        float s = v.w;
        #pragma unroll
        for (int o = 1; o < 32; o <<= 1) {
            float tv = __shfl_up_sync(0xffffffffu, s, o);
            if (lane >= o) s *= tv;
        }
        float e   = __shfl_up_sync(0xffffffffu, s, 1);
        if (lane == 0) e = 1.0f;
        float tot = __shfl_sync(0xffffffffu, s, 31);

        const float ce = carry * e;   // global exclusive prefix for this thread
        v.x *= ce; v.y *= ce; v.z *= ce; v.w *= ce;
        __stcs(&yout[seg + c * 32 + lane], v);

        carry *= tot;
    }
}

extern "C" void kernel_launch(void* const* d_in, const int* in_sizes, int n_in,
                              void* d_out, int out_size) {
    const float* x = (const float*)d_in[0];
    float* y = (float*)d_out;
    const int rows = in_sizes[0] / ROW_LEN;   // 4096
    cumprod_dim1_kernel<<<rows, THREADS>>>(x, y);
}